// round 4
// baseline (speedup 1.0000x reference)
#include <cuda_runtime.h>
#include <math.h>

#define ZN 1024
#define NA 14
#define NAA 21
#define NV 4096          // 16^3
#define NTHREADS 256

// out layout: Cb [ZN*4*3] | div [ZN*4096] | frames [ZN*3*3]
#define DIV_OFF   (ZN * 12)
#define FR_OFF    (ZN * 12 + ZN * NV)

typedef unsigned long long u64;

__device__ __forceinline__ u64 pk2(float lo, float hi) {
    u64 r; asm("mov.b64 %0,{%1,%2};" : "=l"(r) : "f"(lo), "f"(hi)); return r;
}
__device__ __forceinline__ void upk2(u64 v, float &lo, float &hi) {
    asm("mov.b64 {%0,%1},%2;" : "=f"(lo), "=f"(hi) : "l"(v));
}
__device__ __forceinline__ u64 add2(u64 a, u64 b) {
    u64 r; asm("add.rn.f32x2 %0,%1,%2;" : "=l"(r) : "l"(a), "l"(b)); return r;
}
__device__ __forceinline__ u64 mul2(u64 a, u64 b) {
    u64 r; asm("mul.rn.f32x2 %0,%1,%2;" : "=l"(r) : "l"(a), "l"(b)); return r;
}
__device__ __forceinline__ u64 fma2_(u64 a, u64 b, u64 c) {
    u64 r; asm("fma.rn.f32x2 %0,%1,%2,%3;" : "=l"(r) : "l"(a), "l"(b), "l"(c)); return r;
}
__device__ __forceinline__ float rsqrt_fast(float x) {
    float r; asm("rsqrt.approx.f32 %0,%1;" : "=f"(r) : "f"(x)); return r;
}

__global__ __launch_bounds__(NTHREADS, 3) void pp_kernel(
    const float* __restrict__ C,
    const int*   __restrict__ L,
    const float* __restrict__ atom_mask,
    const float* __restrict__ charges,
    float* __restrict__ out)
{
    extern __shared__ float sf[];            // 3 * 4096 floats = 48 KB
    float* sfx = sf;
    float* sfy = sf + NV;
    float* sfz = sf + 2 * NV;
    __shared__ u64 satom[NA * 4];            // per atom: (-Cx,-Cx)(-Cy,-Cy)(-Cz,-Cz)(pc,pc)
    __shared__ float sfr[9];
    __shared__ float sorig[3];

    const int n   = blockIdx.x;
    const int tid = threadIdx.x;
    const float* Cn = C + n * NA * 3;

    if (tid < NA) {
        int lbl = L[n];
        if (lbl == -1) lbl = NAA - 1;
        float cx = Cn[tid * 3 + 0];
        float cy = Cn[tid * 3 + 1];
        float cz = Cn[tid * 3 + 2];
        float pc = charges[lbl * NA + tid] * atom_mask[n * NA + tid];
        satom[tid * 4 + 0] = pk2(-cx, -cx);
        satom[tid * 4 + 1] = pk2(-cy, -cy);
        satom[tid * 4 + 2] = pk2(-cz, -cz);
        satom[tid * 4 + 3] = pk2(pc, pc);
    }
    if (tid == 0) {
        float Nx = Cn[0], Ny = Cn[1], Nz = Cn[2];
        float Ax = Cn[3], Ay = Cn[4], Az = Cn[5];
        float Bx = Cn[6], By = Cn[7], Bz = Cn[8];   // "C" atom
        float b1x = Ax - Nx, b1y = Ay - Ny, b1z = Az - Nz;
        float b2x = Bx - Ax, b2y = By - Ay, b2z = Bz - Az;
        float b3x = b1y * b2z - b1z * b2y;
        float b3y = b1z * b2x - b1x * b2z;
        float b3z = b1x * b2y - b1y * b2x;
        float cbx = Ax - 0.58273431f * b2x + 0.56802827f * b1x - 0.54067466f * b3x;
        float cby = Ay - 0.58273431f * b2y + 0.56802827f * b1y - 0.54067466f * b3y;
        float cbz = Az - 0.58273431f * b2z + 0.56802827f * b1z - 0.54067466f * b3z;
        float yx = cbx - Ax, yy = cby - Ay, yz = cbz - Az;
        float ynrm = fmaxf(sqrtf(yx * yx + yy * yy + yz * yz), 1e-6f);
        float yux = yx / ynrm, yuy = yy / ynrm, yuz = yz / ynrm;
        float xrx = Bx - Nx, xry = By - Ny, xrz = Bz - Nz;
        float xp  = xrx * yux + xry * yuy + xrz * yuz;
        float xx = xrx - xp, xy = xry - xp, xz = xrz - xp;
        float xnrm = fmaxf(sqrtf(xx * xx + xy * xy + xz * xz), 1e-6f);
        float xux = xx / xnrm, xuy = xy / xnrm, xuz = xz / xnrm;
        float zx = xuy * yuz - xuz * yuy;
        float zy = xuz * yux - xux * yuz;
        float zz = xux * yuy - xuy * yux;
        float znrm = fmaxf(sqrtf(zx * zx + zy * zy + zz * zz), 1e-6f);
        float zux = zx / znrm, zuy = zy / znrm, zuz = zz / znrm;

        sfr[0] = xux; sfr[1] = xuy; sfr[2] = xuz;
        sfr[3] = yux; sfr[4] = yuy; sfr[5] = yuz;
        sfr[6] = zux; sfr[7] = zuy; sfr[8] = zuz;
        sorig[0] = cbx; sorig[1] = cby; sorig[2] = cbz;

        float* cbo = out + n * 12;
        cbo[0] = Nx;  cbo[1] = Ny;  cbo[2] = Nz;
        cbo[3] = Ax;  cbo[4] = Ay;  cbo[5] = Az;
        cbo[6] = Bx;  cbo[7] = By;  cbo[8] = Bz;
        cbo[9] = cbx; cbo[10] = cby; cbo[11] = cbz;
        float* fro = out + FR_OFF + n * 9;
        fro[0] = xux; fro[1] = xuy; fro[2] = xuz;
        fro[3] = yux; fro[4] = yuy; fro[5] = yuz;
        fro[6] = zux; fro[7] = zuy; fro[8] = zuz;
    }
    __syncthreads();

    const float fr0 = sfr[0], fr1 = sfr[1], fr2 = sfr[2];
    const float ox = sorig[0], oy = sorig[1], oz = sorig[2];

    // thread owns the x-line; lanes of each f32x2 = voxels x=k (lo) and x=k+8 (hi)
    const float vy = (float)(tid >> 4) - 4.0f;
    const float vz = (float)(tid & 15) - 8.0f;
    float px0 = ox + (-8.0f) * fr0 + vy * sfr[3] + vz * sfr[6];
    float py0 = oy + (-8.0f) * fr1 + vy * sfr[4] + vz * sfr[7];
    float pz0 = oz + (-8.0f) * fr2 + vy * sfr[5] + vz * sfr[8];
    u64 pxp = pk2(px0, px0 + 8.0f * fr0);
    u64 pyp = pk2(py0, py0 + 8.0f * fr1);
    u64 pzp = pk2(pz0, pz0 + 8.0f * fr2);
    const u64 sxp = pk2(fr0, fr0);
    const u64 syp = pk2(fr1, fr1);
    const u64 szp = pk2(fr2, fr2);
    const u64 eps2 = pk2(1e-30f, 1e-30f);

    #pragma unroll 1
    for (int k = 0; k < 8; k++) {
        u64 fxp = 0ULL, fyp = 0ULL, fzp = 0ULL;
        #pragma unroll
        for (int j = 0; j < NA; j++) {
            u64 dx = add2(pxp, satom[j * 4 + 0]);
            u64 dy = add2(pyp, satom[j * 4 + 1]);
            u64 dz = add2(pzp, satom[j * 4 + 2]);
            u64 d2 = fma2_(dx, dx, fma2_(dy, dy, fma2_(dz, dz, eps2)));
            float a, b;
            upk2(d2, a, b);
            // factor = (1/d^3) * min(d^2,1): d>=1 -> 1/d^3 ; d<1 -> 1/d
            float ia = rsqrt_fast(a);
            float ib = rsqrt_fast(b);
            float sa = fminf(a, 1.0f);
            float sb = fminf(b, 1.0f);
            u64 iap = pk2(ia, ib);
            u64 sap = pk2(sa, sb);
            u64 wp = mul2(mul2(mul2(iap, iap), mul2(iap, sap)), satom[j * 4 + 3]);
            fxp = fma2_(wp, dx, fxp);
            fyp = fma2_(wp, dy, fyp);
            fzp = fma2_(wp, dz, fzp);
        }
        // per-lane normalize + store: lane lo -> x=k, lane hi -> x=k+8
        float fxa, fxb, fya, fyb, fza, fzb;
        upk2(fxp, fxa, fxb);
        upk2(fyp, fya, fyb);
        upk2(fzp, fza, fzb);
        float fn2a = fmaxf(fmaf(fxa, fxa, fmaf(fya, fya, fza * fza)), 1e-38f);
        float fn2b = fmaxf(fmaf(fxb, fxb, fmaf(fyb, fyb, fzb * fzb)), 1e-38f);
        float rna = rsqrt_fast(fn2a);
        float rnb = rsqrt_fast(fn2b);
        int i_lo = tid + (k << 8);
        int i_hi = i_lo + 2048;
        sfx[i_lo] = fxa * rna; sfx[i_hi] = fxb * rnb;
        sfy[i_lo] = fya * rna; sfy[i_hi] = fyb * rnb;
        sfz[i_lo] = fza * rna; sfz[i_hi] = fzb * rnb;
        pxp = add2(pxp, sxp);
        pyp = add2(pyp, syp);
        pzp = add2(pzp, szp);
    }
    __syncthreads();

    // ---- divergence (CELL_DIM r = 1) ----
    float* dvo = out + DIV_OFF + n * NV;
    #pragma unroll 1
    for (int k = 0; k < 16; k++) {
        int i = tid + (k << 8);
        int x = k;
        int y = tid >> 4;
        int z = tid & 15;
        float ddx, ddy, ddz;
        if (x == 0)        ddx = sfx[i + 256] - sfx[i];
        else if (x == 15)  ddx = sfx[i] - sfx[i - 256];
        else               ddx = 0.5f * (sfx[i + 256] - sfx[i - 256]);
        if (y == 0)        ddy = sfy[i + 16] - sfy[i];
        else if (y == 15)  ddy = sfy[i] - sfy[i - 16];
        else               ddy = 0.5f * (sfy[i + 16] - sfy[i - 16]);
        if (z == 0)        ddz = sfz[i + 1] - sfz[i];
        else if (z == 15)  ddz = sfz[i] - sfz[i - 1];
        else               ddz = 0.5f * (sfz[i + 1] - sfz[i - 1]);
        dvo[i] = ddx + ddy + ddz;
    }
}

extern "C" void kernel_launch(void* const* d_in, const int* in_sizes, int n_in,
                              void* d_out, int out_size) {
    const float* C         = (const float*)d_in[0];
    const int*   L         = (const int*)d_in[1];
    const float* atom_mask = (const float*)d_in[2];
    const float* charges   = (const float*)d_in[3];
    float* out = (float*)d_out;

    static bool attr_set = false;
    if (!attr_set) {
        cudaFuncSetAttribute(pp_kernel, cudaFuncAttributeMaxDynamicSharedMemorySize, 64 * 1024);
        attr_set = true;
    }
    pp_kernel<<<ZN, NTHREADS, 3 * NV * sizeof(float)>>>(C, L, atom_mask, charges, out);
}

// round 5
// speedup vs baseline: 1.0546x; 1.0546x over previous
#include <cuda_runtime.h>
#include <math.h>

#define ZN 1024
#define NA 14
#define NAA 21
#define NV 4096          // 16^3
#define NTHREADS 256

// out layout: Cb [ZN*4*3] | div [ZN*4096] | frames [ZN*3*3]
#define DIV_OFF   (ZN * 12)
#define FR_OFF    (ZN * 12 + ZN * NV)

typedef unsigned long long u64;

__device__ __forceinline__ u64 pk2(float lo, float hi) {
    u64 r; asm("mov.b64 %0,{%1,%2};" : "=l"(r) : "f"(lo), "f"(hi)); return r;
}
__device__ __forceinline__ void upk2(u64 v, float &lo, float &hi) {
    asm("mov.b64 {%0,%1},%2;" : "=f"(lo), "=f"(hi) : "l"(v));
}
__device__ __forceinline__ u64 add2(u64 a, u64 b) {
    u64 r; asm("add.rn.f32x2 %0,%1,%2;" : "=l"(r) : "l"(a), "l"(b)); return r;
}
__device__ __forceinline__ u64 mul2(u64 a, u64 b) {
    u64 r; asm("mul.rn.f32x2 %0,%1,%2;" : "=l"(r) : "l"(a), "l"(b)); return r;
}
__device__ __forceinline__ u64 fma2_(u64 a, u64 b, u64 c) {
    u64 r; asm("fma.rn.f32x2 %0,%1,%2,%3;" : "=l"(r) : "l"(a), "l"(b), "l"(c)); return r;
}
__device__ __forceinline__ float rsqrt_fast(float x) {
    float r; asm("rsqrt.approx.f32 %0,%1;" : "=f"(r) : "f"(x)); return r;
}

__global__ __launch_bounds__(NTHREADS, 3) void pp_kernel(
    const float* __restrict__ C,
    const int*   __restrict__ L,
    const float* __restrict__ atom_mask,
    const float* __restrict__ charges,
    float* __restrict__ out)
{
    extern __shared__ float sf[];            // 3 * 4096 floats = 48 KB
    float* sfx = sf;
    float* sfy = sf + NV;
    float* sfz = sf + 2 * NV;
    __shared__ alignas(16) u64 satom[NA * 4]; // per atom: (-Cx,-Cx)(-Cy,-Cy)(-Cz,-Cz)(pc,pc)
    __shared__ float sfr[9];
    __shared__ float sorig[3];

    const int n   = blockIdx.x;
    const int tid = threadIdx.x;
    const float* Cn = C + n * NA * 3;

    if (tid < NA) {
        int lbl = L[n];
        if (lbl == -1) lbl = NAA - 1;
        float cx = Cn[tid * 3 + 0];
        float cy = Cn[tid * 3 + 1];
        float cz = Cn[tid * 3 + 2];
        float pc = charges[lbl * NA + tid] * atom_mask[n * NA + tid];
        satom[tid * 4 + 0] = pk2(-cx, -cx);
        satom[tid * 4 + 1] = pk2(-cy, -cy);
        satom[tid * 4 + 2] = pk2(-cz, -cz);
        satom[tid * 4 + 3] = pk2(pc, pc);
    }
    if (tid == 0) {
        float Nx = Cn[0], Ny = Cn[1], Nz = Cn[2];
        float Ax = Cn[3], Ay = Cn[4], Az = Cn[5];
        float Bx = Cn[6], By = Cn[7], Bz = Cn[8];   // "C" atom
        float b1x = Ax - Nx, b1y = Ay - Ny, b1z = Az - Nz;
        float b2x = Bx - Ax, b2y = By - Ay, b2z = Bz - Az;
        float b3x = b1y * b2z - b1z * b2y;
        float b3y = b1z * b2x - b1x * b2z;
        float b3z = b1x * b2y - b1y * b2x;
        float cbx = Ax - 0.58273431f * b2x + 0.56802827f * b1x - 0.54067466f * b3x;
        float cby = Ay - 0.58273431f * b2y + 0.56802827f * b1y - 0.54067466f * b3y;
        float cbz = Az - 0.58273431f * b2z + 0.56802827f * b1z - 0.54067466f * b3z;
        float yx = cbx - Ax, yy = cby - Ay, yz = cbz - Az;
        float ynrm = fmaxf(sqrtf(yx * yx + yy * yy + yz * yz), 1e-6f);
        float yux = yx / ynrm, yuy = yy / ynrm, yuz = yz / ynrm;
        float xrx = Bx - Nx, xry = By - Ny, xrz = Bz - Nz;
        float xp  = xrx * yux + xry * yuy + xrz * yuz;
        float xx = xrx - xp, xy = xry - xp, xz = xrz - xp;
        float xnrm = fmaxf(sqrtf(xx * xx + xy * xy + xz * xz), 1e-6f);
        float xux = xx / xnrm, xuy = xy / xnrm, xuz = xz / xnrm;
        float zx = xuy * yuz - xuz * yuy;
        float zy = xuz * yux - xux * yuz;
        float zz = xux * yuy - xuy * yux;
        float znrm = fmaxf(sqrtf(zx * zx + zy * zy + zz * zz), 1e-6f);
        float zux = zx / znrm, zuy = zy / znrm, zuz = zz / znrm;

        sfr[0] = xux; sfr[1] = xuy; sfr[2] = xuz;
        sfr[3] = yux; sfr[4] = yuy; sfr[5] = yuz;
        sfr[6] = zux; sfr[7] = zuy; sfr[8] = zuz;
        sorig[0] = cbx; sorig[1] = cby; sorig[2] = cbz;

        float* cbo = out + n * 12;
        cbo[0] = Nx;  cbo[1] = Ny;  cbo[2] = Nz;
        cbo[3] = Ax;  cbo[4] = Ay;  cbo[5] = Az;
        cbo[6] = Bx;  cbo[7] = By;  cbo[8] = Bz;
        cbo[9] = cbx; cbo[10] = cby; cbo[11] = cbz;
        float* fro = out + FR_OFF + n * 9;
        fro[0] = xux; fro[1] = xuy; fro[2] = xuz;
        fro[3] = yux; fro[4] = yuy; fro[5] = yuz;
        fro[6] = zux; fro[7] = zuy; fro[8] = zuz;
    }
    __syncthreads();

    const float fr0 = sfr[0], fr1 = sfr[1], fr2 = sfr[2];
    const float ox = sorig[0], oy = sorig[1], oz = sorig[2];

    // thread owns the x-line; 4 voxels per k-iter:
    //   pair A lanes = (x=k,   x=k+8)
    //   pair B lanes = (x=k+4, x=k+12)
    const float vy = (float)(tid >> 4) - 4.0f;
    const float vz = (float)(tid & 15) - 8.0f;
    float px0 = ox + (-8.0f) * fr0 + vy * sfr[3] + vz * sfr[6];
    float py0 = oy + (-8.0f) * fr1 + vy * sfr[4] + vz * sfr[7];
    float pz0 = oz + (-8.0f) * fr2 + vy * sfr[5] + vz * sfr[8];
    u64 pxA = pk2(px0,              px0 + 8.0f * fr0);
    u64 pyA = pk2(py0,              py0 + 8.0f * fr1);
    u64 pzA = pk2(pz0,              pz0 + 8.0f * fr2);
    u64 pxB = pk2(px0 + 4.0f * fr0, px0 + 12.0f * fr0);
    u64 pyB = pk2(py0 + 4.0f * fr1, py0 + 12.0f * fr1);
    u64 pzB = pk2(pz0 + 4.0f * fr2, pz0 + 12.0f * fr2);
    const u64 sxp = pk2(fr0, fr0);
    const u64 syp = pk2(fr1, fr1);
    const u64 szp = pk2(fr2, fr2);
    const u64 eps2 = pk2(1e-30f, 1e-30f);

    #pragma unroll 1
    for (int k = 0; k < 4; k++) {
        u64 fxA = 0ULL, fyA = 0ULL, fzA = 0ULL;
        u64 fxB = 0ULL, fyB = 0ULL, fzB = 0ULL;
        #pragma unroll
        for (int j = 0; j < NA; j++) {
            ulonglong2 t0 = *reinterpret_cast<const ulonglong2*>(satom + j * 4);
            ulonglong2 t1 = *reinterpret_cast<const ulonglong2*>(satom + j * 4 + 2);
            // pair A
            u64 dxA = add2(pxA, t0.x);
            u64 dyA = add2(pyA, t0.y);
            u64 dzA = add2(pzA, t1.x);
            u64 d2A = fma2_(dxA, dxA, fma2_(dyA, dyA, fma2_(dzA, dzA, eps2)));
            // pair B
            u64 dxB = add2(pxB, t0.x);
            u64 dyB = add2(pyB, t0.y);
            u64 dzB = add2(pzB, t1.x);
            u64 d2B = fma2_(dxB, dxB, fma2_(dyB, dyB, fma2_(dzB, dzB, eps2)));

            float aA, bA, aB, bB;
            upk2(d2A, aA, bA);
            upk2(d2B, aB, bB);
            float iaA = rsqrt_fast(aA);
            float ibA = rsqrt_fast(bA);
            float iaB = rsqrt_fast(aB);
            float ibB = rsqrt_fast(bB);
            float saA = fminf(aA, 1.0f);
            float sbA = fminf(bA, 1.0f);
            float saB = fminf(aB, 1.0f);
            float sbB = fminf(bB, 1.0f);
            u64 iA = pk2(iaA, ibA);
            u64 sA = pk2(saA, sbA);
            u64 iB = pk2(iaB, ibB);
            u64 sB = pk2(saB, sbB);
            u64 wA = mul2(mul2(mul2(iA, iA), mul2(iA, sA)), t1.y);
            u64 wB = mul2(mul2(mul2(iB, iB), mul2(iB, sB)), t1.y);
            fxA = fma2_(wA, dxA, fxA);
            fyA = fma2_(wA, dyA, fyA);
            fzA = fma2_(wA, dzA, fzA);
            fxB = fma2_(wB, dxB, fxB);
            fyB = fma2_(wB, dyB, fyB);
            fzB = fma2_(wB, dzB, fzB);
        }
        // normalize + store: A -> x=k, x=k+8 ; B -> x=k+4, x=k+12
        float v0x, v1x, v0y, v1y, v0z, v1z;
        upk2(fxA, v0x, v1x); upk2(fyA, v0y, v1y); upk2(fzA, v0z, v1z);
        {
            float fn0 = fmaxf(fmaf(v0x, v0x, fmaf(v0y, v0y, v0z * v0z)), 1e-38f);
            float fn1 = fmaxf(fmaf(v1x, v1x, fmaf(v1y, v1y, v1z * v1z)), 1e-38f);
            float r0 = rsqrt_fast(fn0), r1 = rsqrt_fast(fn1);
            int i0 = tid + (k << 8), i1 = i0 + 2048;
            sfx[i0] = v0x * r0; sfx[i1] = v1x * r1;
            sfy[i0] = v0y * r0; sfy[i1] = v1y * r1;
            sfz[i0] = v0z * r0; sfz[i1] = v1z * r1;
        }
        upk2(fxB, v0x, v1x); upk2(fyB, v0y, v1y); upk2(fzB, v0z, v1z);
        {
            float fn0 = fmaxf(fmaf(v0x, v0x, fmaf(v0y, v0y, v0z * v0z)), 1e-38f);
            float fn1 = fmaxf(fmaf(v1x, v1x, fmaf(v1y, v1y, v1z * v1z)), 1e-38f);
            float r0 = rsqrt_fast(fn0), r1 = rsqrt_fast(fn1);
            int i0 = tid + (k << 8) + 1024, i1 = i0 + 2048;
            sfx[i0] = v0x * r0; sfx[i1] = v1x * r1;
            sfy[i0] = v0y * r0; sfy[i1] = v1y * r1;
            sfz[i0] = v0z * r0; sfz[i1] = v1z * r1;
        }
        pxA = add2(pxA, sxp); pyA = add2(pyA, syp); pzA = add2(pzA, szp);
        pxB = add2(pxB, sxp); pyB = add2(pyB, syp); pzB = add2(pzB, szp);
    }
    __syncthreads();

    // ---- divergence (CELL_DIM r = 1) ----
    float* dvo = out + DIV_OFF + n * NV;
    #pragma unroll 1
    for (int k = 0; k < 16; k++) {
        int i = tid + (k << 8);
        int x = k;
        int y = tid >> 4;
        int z = tid & 15;
        float ddx, ddy, ddz;
        if (x == 0)        ddx = sfx[i + 256] - sfx[i];
        else if (x == 15)  ddx = sfx[i] - sfx[i - 256];
        else               ddx = 0.5f * (sfx[i + 256] - sfx[i - 256]);
        if (y == 0)        ddy = sfy[i + 16] - sfy[i];
        else if (y == 15)  ddy = sfy[i] - sfy[i - 16];
        else               ddy = 0.5f * (sfy[i + 16] - sfy[i - 16]);
        if (z == 0)        ddz = sfz[i + 1] - sfz[i];
        else if (z == 15)  ddz = sfz[i] - sfz[i - 1];
        else               ddz = 0.5f * (sfz[i + 1] - sfz[i - 1]);
        dvo[i] = ddx + ddy + ddz;
    }
}

extern "C" void kernel_launch(void* const* d_in, const int* in_sizes, int n_in,
                              void* d_out, int out_size) {
    const float* C         = (const float*)d_in[0];
    const int*   L         = (const int*)d_in[1];
    const float* atom_mask = (const float*)d_in[2];
    const float* charges   = (const float*)d_in[3];
    float* out = (float*)d_out;

    static bool attr_set = false;
    if (!attr_set) {
        cudaFuncSetAttribute(pp_kernel, cudaFuncAttributeMaxDynamicSharedMemorySize, 64 * 1024);
        attr_set = true;
    }
    pp_kernel<<<ZN, NTHREADS, 3 * NV * sizeof(float)>>>(C, L, atom_mask, charges, out);
}